// round 13
// baseline (speedup 1.0000x reference)
#include <cuda_runtime.h>

// CausalRevIN: B=16, T=8192, C=128, fp32.
// Multi-wave pipelined scan: 2048 CTAs (tile=64t, 4 warps x 16t), ticket-ordered,
// windowed warp-parallel decoupled lookback x2 (r8 machinery).

#define BB 16
#define TT 8192
#define TILE_T 64
#define SPW 16                  // timesteps per warp strip
#define SPB 128                 // tiles per series
#define NTILE (BB * SPB)        // 2048

#define STD_MIN 1e-5f
#define MAX_VAL 100.0f

__device__ float4 g_aggA_nm[NTILE * 32];
__device__ float4 g_aggA_x [NTILE * 32];
__device__ float4 g_incA_nm[NTILE * 32];
__device__ float4 g_incA_x [NTILE * 32];
__device__ float4 g_aggC   [NTILE * 32];
__device__ float4 g_incC   [NTILE * 32];
__device__ int    g_stateA [NTILE];
__device__ int    g_stateC [NTILE];
__device__ int    g_ticket;

__global__ void k_init() {
    int i = blockIdx.x * blockDim.x + threadIdx.x;
    if (i < NTILE) { g_stateA[i] = 0; g_stateC[i] = 0; }
    if (i == 0) g_ticket = 0;
}

__device__ __forceinline__ void f4add(float4& a, const float4 b) {
    a.x += b.x; a.y += b.y; a.z += b.z; a.w += b.w;
}

__global__ void __launch_bounds__(128, 7) k_main(const float* __restrict__ x,
                                                 const float* __restrict__ m,
                                                 float* __restrict__ out) {
    __shared__ float4 s_a[128];
    __shared__ float4 s_b[128];
    __shared__ int sh_tile;

    const int tid = threadIdx.x;
    if (tid == 0) sh_tile = atomicAdd(&g_ticket, 1);
    __syncthreads();
    const int tile = sh_tile;            // start-order = dependency-safe order
    const int b    = tile >> 7;
    const int seg  = tile & (SPB - 1);
    const int w    = tid >> 5;
    const int l    = tid & 31;
    const int bbase = b << 7;

    const float4* __restrict__ x4 = (const float4*)x;
    const float4* __restrict__ m4 = (const float4*)m;
    float4* __restrict__ o4 = (float4*)out;
    const int rowbase = (b * TT + seg * TILE_T + w * SPW) * 32 + l;

    // ================= Phase 1: load, pack mask bits, sum x =================
    float4 sx = make_float4(0.f, 0.f, 0.f, 0.f);
    unsigned nb0 = 0, nb1 = 0, nb2 = 0, nb3 = 0;
    #pragma unroll
    for (int t = 0; t < SPW; t++) {
        float4 xv = x4[rowbase + t * 32];
        float4 mv = __ldcs(&m4[rowbase + t * 32]);
        f4add(sx, xv);
        if (mv.x == 0.f) nb0 |= 1u << t;
        if (mv.y == 0.f) nb1 |= 1u << t;
        if (mv.z == 0.f) nb2 |= 1u << t;
        if (mv.w == 0.f) nb3 |= 1u << t;
    }
    float4 snm = make_float4((float)__popc(nb0), (float)__popc(nb1),
                             (float)__popc(nb2), (float)__popc(nb3));
    s_a[tid] = snm; s_b[tid] = sx;
    __syncthreads();

    // exclusive prefix over strips (same lane) + CTA totals for warp 0
    float4 we_nm = make_float4(0.f, 0.f, 0.f, 0.f);
    float4 we_x  = make_float4(0.f, 0.f, 0.f, 0.f);
    for (int ww = 0; ww < w; ww++) { f4add(we_nm, s_a[ww * 32 + l]); f4add(we_x, s_b[ww * 32 + l]); }
    float4 tot_nm, tot_x;
    if (w == 0) {
        tot_nm = s_a[l];            tot_x = s_b[l];
        f4add(tot_nm, s_a[32 + l]); f4add(tot_x, s_b[32 + l]);
        f4add(tot_nm, s_a[64 + l]); f4add(tot_x, s_b[64 + l]);
        f4add(tot_nm, s_a[96 + l]); f4add(tot_x, s_b[96 + l]);
    }
    __syncthreads();

    // ================= Lookback A (warp 0) =================
    if (w == 0) {
        float4 ex_nm = make_float4(0.f, 0.f, 0.f, 0.f);
        float4 ex_x  = make_float4(0.f, 0.f, 0.f, 0.f);
        if (seg != 0) {
            g_aggA_nm[tile * 32 + l] = tot_nm;
            g_aggA_x [tile * 32 + l] = tot_x;
            __threadfence();
            __syncwarp();
            if (l == 0) atomicExch(&g_stateA[tile], 1);

            int p_end = seg;
            for (;;) {
                int cnt = p_end < 32 ? p_end : 32;
                int s = 2;
                if (l < cnt) {
                    int pp = bbase + p_end - 1 - l;
                    do { s = atomicAdd(&g_stateA[pp], 0); } while (s == 0);
                }
                unsigned incmask = __ballot_sync(0xffffffffu, (s == 2) && (l < cnt));
                __threadfence();
                int li = incmask ? (__ffs(incmask) - 1) : -1;
                int nagg = (li >= 0) ? li : cnt;
                for (int j = 0; j < nagg; j++) {
                    int pidx = (bbase + p_end - 1 - j) * 32 + l;
                    f4add(ex_nm, __ldcg(&g_aggA_nm[pidx]));
                    f4add(ex_x,  __ldcg(&g_aggA_x [pidx]));
                }
                if (li >= 0) {
                    int pidx = (bbase + p_end - 1 - li) * 32 + l;
                    f4add(ex_nm, __ldcg(&g_incA_nm[pidx]));
                    f4add(ex_x,  __ldcg(&g_incA_x [pidx]));
                    break;
                }
                p_end -= cnt;
            }
        }
        float4 in_nm = ex_nm, in_x = ex_x;
        f4add(in_nm, tot_nm); f4add(in_x, tot_x);
        g_incA_nm[tile * 32 + l] = in_nm;
        g_incA_x [tile * 32 + l] = in_x;
        __threadfence();
        __syncwarp();
        if (l == 0) atomicExch(&g_stateA[tile], 2);
        s_a[l] = ex_nm; s_b[l] = ex_x;
    }
    __syncthreads();
    float4 base_n = s_a[l], base_x = s_b[l];
    f4add(base_n, we_nm); f4add(base_x, we_x);

    // ================= Phase 2: local sum of ((x-mean)*nm)^2 =================
    float4 cn = base_n, cx = base_x;
    float4 lss = make_float4(0.f, 0.f, 0.f, 0.f);
    #pragma unroll
    for (int t = 0; t < SPW; t++) {
        float4 xv = x4[rowbase + t * 32];
        #define STEP2(k, bits)                                            \
        {                                                                 \
            float nm = (bits & (1u << t)) ? 1.f : 0.f;                    \
            cn.k += nm; cx.k += xv.k;                                     \
            float n = fmaxf(cn.k, 1.f);                                   \
            float mean = cx.k * __fdividef(1.f, n);                       \
            float d = (xv.k - mean) * nm;                                 \
            lss.k += d * d;                                               \
        }
        STEP2(x, nb0) STEP2(y, nb1) STEP2(z, nb2) STEP2(w, nb3)
        #undef STEP2
    }
    __syncthreads();
    s_a[tid] = lss;
    __syncthreads();
    float4 we_s = make_float4(0.f, 0.f, 0.f, 0.f);
    for (int ww = 0; ww < w; ww++) f4add(we_s, s_a[ww * 32 + l]);
    float4 tot_s;
    if (w == 0) {
        tot_s = s_a[l];
        f4add(tot_s, s_a[32 + l]); f4add(tot_s, s_a[64 + l]); f4add(tot_s, s_a[96 + l]);
    }
    __syncthreads();

    // ================= Lookback C (warp 0) =================
    if (w == 0) {
        float4 ex_s = make_float4(0.f, 0.f, 0.f, 0.f);
        if (seg != 0) {
            g_aggC[tile * 32 + l] = tot_s;
            __threadfence();
            __syncwarp();
            if (l == 0) atomicExch(&g_stateC[tile], 1);

            int p_end = seg;
            for (;;) {
                int cnt = p_end < 32 ? p_end : 32;
                int s = 2;
                if (l < cnt) {
                    int pp = bbase + p_end - 1 - l;
                    do { s = atomicAdd(&g_stateC[pp], 0); } while (s == 0);
                }
                unsigned incmask = __ballot_sync(0xffffffffu, (s == 2) && (l < cnt));
                __threadfence();
                int li = incmask ? (__ffs(incmask) - 1) : -1;
                int nagg = (li >= 0) ? li : cnt;
                for (int j = 0; j < nagg; j++)
                    f4add(ex_s, __ldcg(&g_aggC[(bbase + p_end - 1 - j) * 32 + l]));
                if (li >= 0) {
                    f4add(ex_s, __ldcg(&g_incC[(bbase + p_end - 1 - li) * 32 + l]));
                    break;
                }
                p_end -= cnt;
            }
        }
        float4 in_s = ex_s; f4add(in_s, tot_s);
        g_incC[tile * 32 + l] = in_s;
        __threadfence();
        __syncwarp();
        if (l == 0) atomicExch(&g_stateC[tile], 2);
        s_a[l] = ex_s;
    }
    __syncthreads();
    float4 base_s = s_a[l];
    f4add(base_s, we_s);

    // ================= Phase 3: normalize + clip, write out =================
    cn = base_n; cx = base_x;
    float4 cs = base_s;
    const float VMIN = STD_MIN * STD_MIN;
    #pragma unroll
    for (int t = 0; t < SPW; t++) {
        float4 xv = __ldcs(&x4[rowbase + t * 32]);
        float4 ov;
        #define STEP3(k, bits)                                            \
        {                                                                 \
            float nm = (bits & (1u << t)) ? 1.f : 0.f;                    \
            cn.k += nm; cx.k += xv.k;                                     \
            float n = fmaxf(cn.k, 1.f);                                   \
            float rn = __fdividef(1.f, n);                                \
            float mean = cx.k * rn;                                       \
            float num = xv.k - mean;                                      \
            float d = num * nm;                                           \
            cs.k += d * d;                                                \
            float var = cs.k * rn;                                        \
            float res = (var > VMIN) ? num * rsqrtf(var) : num;           \
            ov.k = fminf(fmaxf(res, -MAX_VAL), MAX_VAL);                  \
        }
        STEP3(x, nb0) STEP3(y, nb1) STEP3(z, nb2) STEP3(w, nb3)
        #undef STEP3
        __stcs(&o4[rowbase + t * 32], ov);
    }
}

extern "C" void kernel_launch(void* const* d_in, const int* in_sizes, int n_in,
                              void* d_out, int out_size) {
    const float* x = (const float*)d_in[0];
    const float* m = (const float*)d_in[1];
    float* out = (float*)d_out;

    k_init<<<(NTILE + 255) / 256, 256>>>();
    k_main<<<NTILE, 128>>>(x, m, out);
}

// round 14
// speedup vs baseline: 1.4736x; 1.4736x over previous
#include <cuda_runtime.h>
#include <cuda_fp16.h>

// CausalRevIN: B=16, T=8192, C=128, fp32.
// r8 structure + fp16 SMEM x-tile: phase 1 stages x as half2 in SMEM,
// phases 2/3 read LDS instead of re-reading x through L2.

#define BB 16
#define TT 8192
#define TILE_T 128
#define SPW 32
#define SPB 64                  // tiles per series
#define NTILE (BB * SPB)        // 1024

#define STD_MIN 1e-5f
#define MAX_VAL 100.0f

__device__ float4 g_aggA_nm[NTILE * 32];
__device__ float4 g_aggA_x [NTILE * 32];
__device__ float4 g_incA_nm[NTILE * 32];
__device__ float4 g_incA_x [NTILE * 32];
__device__ float4 g_aggC   [NTILE * 32];
__device__ float4 g_incC   [NTILE * 32];
__device__ int    g_stateA [NTILE];
__device__ int    g_stateC [NTILE];
__device__ int    g_ticket;

__global__ void k_init() {
    int i = blockIdx.x * blockDim.x + threadIdx.x;
    if (i < NTILE) { g_stateA[i] = 0; g_stateC[i] = 0; }
    if (i == 0) g_ticket = 0;
}

__device__ __forceinline__ void f4add(float4& a, const float4 b) {
    a.x += b.x; a.y += b.y; a.z += b.z; a.w += b.w;
}

__global__ void __launch_bounds__(128, 6) k_main(const float* __restrict__ x,
                                                 const float* __restrict__ m,
                                                 float* __restrict__ out) {
    __shared__ uint2  xh[TILE_T * 32];   // 32 KB: 4 halves per (t, lane)
    __shared__ float4 s_a[128];
    __shared__ float4 s_b[128];
    __shared__ int sh_tile;

    const int tid = threadIdx.x;
    if (tid == 0) sh_tile = atomicAdd(&g_ticket, 1);
    __syncthreads();
    const int tile = sh_tile;            // start-order -> safe across waves
    const int b    = tile >> 6;
    const int seg  = tile & (SPB - 1);
    const int w    = tid >> 5;
    const int l    = tid & 31;
    const int bbase = b << 6;

    const float4* __restrict__ x4 = (const float4*)x;
    const float4* __restrict__ m4 = (const float4*)m;
    float4* __restrict__ o4 = (float4*)out;
    const int rowbase = (b * TT + seg * TILE_T + w * SPW) * 32 + l;
    const int shbase  = w * SPW * 32 + l;

    // ================= Phase 1: load, pack mask bits, sum x, stage x as fp16 =================
    float4 sx = make_float4(0.f, 0.f, 0.f, 0.f);
    unsigned nb0 = 0, nb1 = 0, nb2 = 0, nb3 = 0;
    #pragma unroll 8
    for (int t = 0; t < SPW; t++) {
        float4 xv = __ldcs(&x4[rowbase + t * 32]);
        float4 mv = __ldcs(&m4[rowbase + t * 32]);
        f4add(sx, xv);
        if (mv.x == 0.f) nb0 |= 1u << t;
        if (mv.y == 0.f) nb1 |= 1u << t;
        if (mv.z == 0.f) nb2 |= 1u << t;
        if (mv.w == 0.f) nb3 |= 1u << t;
        __half2 h01 = __floats2half2_rn(xv.x, xv.y);
        __half2 h23 = __floats2half2_rn(xv.z, xv.w);
        uint2 u;
        u.x = *(unsigned*)&h01;
        u.y = *(unsigned*)&h23;
        xh[shbase + t * 32] = u;
    }
    float4 snm = make_float4((float)__popc(nb0), (float)__popc(nb1),
                             (float)__popc(nb2), (float)__popc(nb3));
    s_a[tid] = snm; s_b[tid] = sx;
    __syncthreads();

    // exclusive prefix over warps (same lane) + CTA totals for warp 0
    float4 we_nm = make_float4(0.f, 0.f, 0.f, 0.f);
    float4 we_x  = make_float4(0.f, 0.f, 0.f, 0.f);
    for (int ww = 0; ww < w; ww++) { f4add(we_nm, s_a[ww * 32 + l]); f4add(we_x, s_b[ww * 32 + l]); }
    float4 tot_nm, tot_x;
    if (w == 0) {
        tot_nm = s_a[l];            tot_x = s_b[l];
        f4add(tot_nm, s_a[32 + l]); f4add(tot_x, s_b[32 + l]);
        f4add(tot_nm, s_a[64 + l]); f4add(tot_x, s_b[64 + l]);
        f4add(tot_nm, s_a[96 + l]); f4add(tot_x, s_b[96 + l]);
    }
    __syncthreads();

    // ================= Lookback A (warp 0) =================
    if (w == 0) {
        float4 ex_nm = make_float4(0.f, 0.f, 0.f, 0.f);
        float4 ex_x  = make_float4(0.f, 0.f, 0.f, 0.f);
        if (seg != 0) {
            g_aggA_nm[tile * 32 + l] = tot_nm;
            g_aggA_x [tile * 32 + l] = tot_x;
            __threadfence();
            __syncwarp();
            if (l == 0) atomicExch(&g_stateA[tile], 1);

            int p_end = seg;
            for (;;) {
                int cnt = p_end < 32 ? p_end : 32;
                int s = 2;
                if (l < cnt) {
                    int pp = bbase + p_end - 1 - l;
                    do { s = atomicAdd(&g_stateA[pp], 0); } while (s == 0);
                }
                unsigned incmask = __ballot_sync(0xffffffffu, (s == 2) && (l < cnt));
                __threadfence();
                int li = incmask ? (__ffs(incmask) - 1) : -1;
                int nagg = (li >= 0) ? li : cnt;
                for (int j = 0; j < nagg; j++) {
                    int pidx = (bbase + p_end - 1 - j) * 32 + l;
                    f4add(ex_nm, __ldcg(&g_aggA_nm[pidx]));
                    f4add(ex_x,  __ldcg(&g_aggA_x [pidx]));
                }
                if (li >= 0) {
                    int pidx = (bbase + p_end - 1 - li) * 32 + l;
                    f4add(ex_nm, __ldcg(&g_incA_nm[pidx]));
                    f4add(ex_x,  __ldcg(&g_incA_x [pidx]));
                    break;
                }
                p_end -= cnt;
            }
        }
        float4 in_nm = ex_nm, in_x = ex_x;
        f4add(in_nm, tot_nm); f4add(in_x, tot_x);
        g_incA_nm[tile * 32 + l] = in_nm;
        g_incA_x [tile * 32 + l] = in_x;
        __threadfence();
        __syncwarp();
        if (l == 0) atomicExch(&g_stateA[tile], 2);
        s_a[l] = ex_nm; s_b[l] = ex_x;
    }
    __syncthreads();
    float4 base_n = s_a[l], base_x = s_b[l];
    f4add(base_n, we_nm); f4add(base_x, we_x);

    // ================= Phase 2: local sum of ((x-mean)*nm)^2 (x from SMEM fp16) =================
    float4 cn = base_n, cx = base_x;
    float4 lss = make_float4(0.f, 0.f, 0.f, 0.f);
    #pragma unroll 8
    for (int t = 0; t < SPW; t++) {
        uint2 u = xh[shbase + t * 32];
        float2 f01 = __half22float2(*(__half2*)&u.x);
        float2 f23 = __half22float2(*(__half2*)&u.y);
        float4 xv = make_float4(f01.x, f01.y, f23.x, f23.y);
        #define STEP2(k, bits)                                            \
        {                                                                 \
            float nm = (bits & (1u << t)) ? 1.f : 0.f;                    \
            cn.k += nm; cx.k += xv.k;                                     \
            float n = fmaxf(cn.k, 1.f);                                   \
            float mean = cx.k * __fdividef(1.f, n);                       \
            float d = (xv.k - mean) * nm;                                 \
            lss.k += d * d;                                               \
        }
        STEP2(x, nb0) STEP2(y, nb1) STEP2(z, nb2) STEP2(w, nb3)
        #undef STEP2
    }
    __syncthreads();
    s_a[tid] = lss;
    __syncthreads();
    float4 we_s = make_float4(0.f, 0.f, 0.f, 0.f);
    for (int ww = 0; ww < w; ww++) f4add(we_s, s_a[ww * 32 + l]);
    float4 tot_s;
    if (w == 0) {
        tot_s = s_a[l];
        f4add(tot_s, s_a[32 + l]); f4add(tot_s, s_a[64 + l]); f4add(tot_s, s_a[96 + l]);
    }
    __syncthreads();

    // ================= Lookback C (warp 0) =================
    if (w == 0) {
        float4 ex_s = make_float4(0.f, 0.f, 0.f, 0.f);
        if (seg != 0) {
            g_aggC[tile * 32 + l] = tot_s;
            __threadfence();
            __syncwarp();
            if (l == 0) atomicExch(&g_stateC[tile], 1);

            int p_end = seg;
            for (;;) {
                int cnt = p_end < 32 ? p_end : 32;
                int s = 2;
                if (l < cnt) {
                    int pp = bbase + p_end - 1 - l;
                    do { s = atomicAdd(&g_stateC[pp], 0); } while (s == 0);
                }
                unsigned incmask = __ballot_sync(0xffffffffu, (s == 2) && (l < cnt));
                __threadfence();
                int li = incmask ? (__ffs(incmask) - 1) : -1;
                int nagg = (li >= 0) ? li : cnt;
                for (int j = 0; j < nagg; j++)
                    f4add(ex_s, __ldcg(&g_aggC[(bbase + p_end - 1 - j) * 32 + l]));
                if (li >= 0) {
                    f4add(ex_s, __ldcg(&g_incC[(bbase + p_end - 1 - li) * 32 + l]));
                    break;
                }
                p_end -= cnt;
            }
        }
        float4 in_s = ex_s; f4add(in_s, tot_s);
        g_incC[tile * 32 + l] = in_s;
        __threadfence();
        __syncwarp();
        if (l == 0) atomicExch(&g_stateC[tile], 2);
        s_a[l] = ex_s;
    }
    __syncthreads();
    float4 base_s = s_a[l];
    f4add(base_s, we_s);

    // ================= Phase 3: normalize + clip, write out (x from SMEM fp16) =================
    cn = base_n; cx = base_x;
    float4 cs = base_s;
    const float VMIN = STD_MIN * STD_MIN;
    #pragma unroll 8
    for (int t = 0; t < SPW; t++) {
        uint2 u = xh[shbase + t * 32];
        float2 f01 = __half22float2(*(__half2*)&u.x);
        float2 f23 = __half22float2(*(__half2*)&u.y);
        float4 xv = make_float4(f01.x, f01.y, f23.x, f23.y);
        float4 ov;
        #define STEP3(k, bits)                                            \
        {                                                                 \
            float nm = (bits & (1u << t)) ? 1.f : 0.f;                    \
            cn.k += nm; cx.k += xv.k;                                     \
            float n = fmaxf(cn.k, 1.f);                                   \
            float rn = __fdividef(1.f, n);                                \
            float mean = cx.k * rn;                                       \
            float num = xv.k - mean;                                      \
            float d = num * nm;                                           \
            cs.k += d * d;                                                \
            float var = cs.k * rn;                                        \
            float res = (var > VMIN) ? num * rsqrtf(var) : num;           \
            ov.k = fminf(fmaxf(res, -MAX_VAL), MAX_VAL);                  \
        }
        STEP3(x, nb0) STEP3(y, nb1) STEP3(z, nb2) STEP3(w, nb3)
        #undef STEP3
        __stcs(&o4[rowbase + t * 32], ov);
    }
}

extern "C" void kernel_launch(void* const* d_in, const int* in_sizes, int n_in,
                              void* d_out, int out_size) {
    const float* x = (const float*)d_in[0];
    const float* m = (const float*)d_in[1];
    float* out = (float*)d_out;

    k_init<<<(NTILE + 255) / 256, 256>>>();
    k_main<<<NTILE, 128>>>(x, m, out);
}

// round 15
// speedup vs baseline: 1.5912x; 1.0798x over previous
#include <cuda_runtime.h>

// CausalRevIN: B=16, T=8192, C=128, fp32.
// r8 structure (1024 CTA-tiles, 4 warps x 32t, windowed lookback, atomic polls)
// + epoch-encoded flags derived from a never-reset ticket -> NO init kernel.

#define BB 16
#define TT 8192
#define TILE_T 128
#define SPW 32
#define SPB 64                  // tiles per series
#define NTILE (BB * SPB)        // 1024

#define STD_MIN 1e-5f
#define MAX_VAL 100.0f

__device__ float4 g_aggA_nm[NTILE * 32];
__device__ float4 g_aggA_x [NTILE * 32];
__device__ float4 g_incA_nm[NTILE * 32];
__device__ float4 g_incA_x [NTILE * 32];
__device__ float4 g_aggC   [NTILE * 32];
__device__ float4 g_incC   [NTILE * 32];
__device__ int    g_stateA [NTILE];    // zero-init at module load; never reset
__device__ int    g_stateC [NTILE];
__device__ unsigned g_ticket;          // never reset; epoch = ticket / NTILE

__device__ __forceinline__ void f4add(float4& a, const float4 b) {
    a.x += b.x; a.y += b.y; a.z += b.z; a.w += b.w;
}

__device__ __forceinline__ float rcpa(float x) {
    float r; asm("rcp.approx.f32 %0, %1;" : "=f"(r) : "f"(x)); return r;
}

__global__ void __launch_bounds__(128, 7) k_main(const float* __restrict__ x,
                                                 const float* __restrict__ m,
                                                 float* __restrict__ out) {
    __shared__ float4 s_a[128];
    __shared__ float4 s_b[128];
    __shared__ unsigned sh_ticket;

    const int tid = threadIdx.x;
    if (tid == 0) sh_ticket = atomicAdd(&g_ticket, 1u);
    __syncthreads();
    const unsigned traw = sh_ticket;
    const int tile  = (int)(traw & (NTILE - 1));     // launch-local tile id
    const int FLAG_AGG = (int)((traw >> 10) * 2u + 1u);  // epoch*2+1
    const int FLAG_INC = FLAG_AGG + 1;
    const int b    = tile >> 6;
    const int seg  = tile & (SPB - 1);
    const int w    = tid >> 5;
    const int l    = tid & 31;
    const int bbase = b << 6;

    const float4* __restrict__ x4 = (const float4*)x;
    const float4* __restrict__ m4 = (const float4*)m;
    float4* __restrict__ o4 = (float4*)out;
    const int rowbase = (b * TT + seg * TILE_T + w * SPW) * 32 + l;

    // ================= Phase 1: load, pack mask bits, sum x =================
    float4 sx = make_float4(0.f, 0.f, 0.f, 0.f);
    unsigned nb0 = 0, nb1 = 0, nb2 = 0, nb3 = 0;
    #pragma unroll 8
    for (int t = 0; t < SPW; t++) {
        float4 xv = x4[rowbase + t * 32];
        float4 mv = __ldcs(&m4[rowbase + t * 32]);
        f4add(sx, xv);
        if (mv.x == 0.f) nb0 |= 1u << t;
        if (mv.y == 0.f) nb1 |= 1u << t;
        if (mv.z == 0.f) nb2 |= 1u << t;
        if (mv.w == 0.f) nb3 |= 1u << t;
    }
    float4 snm = make_float4((float)__popc(nb0), (float)__popc(nb1),
                             (float)__popc(nb2), (float)__popc(nb3));
    s_a[tid] = snm; s_b[tid] = sx;
    __syncthreads();

    // exclusive prefix over warps (same lane) + CTA totals for warp 0
    float4 we_nm = make_float4(0.f, 0.f, 0.f, 0.f);
    float4 we_x  = make_float4(0.f, 0.f, 0.f, 0.f);
    for (int ww = 0; ww < w; ww++) { f4add(we_nm, s_a[ww * 32 + l]); f4add(we_x, s_b[ww * 32 + l]); }
    float4 tot_nm, tot_x;
    if (w == 0) {
        tot_nm = s_a[l];            tot_x = s_b[l];
        f4add(tot_nm, s_a[32 + l]); f4add(tot_x, s_b[32 + l]);
        f4add(tot_nm, s_a[64 + l]); f4add(tot_x, s_b[64 + l]);
        f4add(tot_nm, s_a[96 + l]); f4add(tot_x, s_b[96 + l]);
    }
    __syncthreads();

    // ================= Lookback A (warp 0) =================
    if (w == 0) {
        float4 ex_nm = make_float4(0.f, 0.f, 0.f, 0.f);
        float4 ex_x  = make_float4(0.f, 0.f, 0.f, 0.f);
        if (seg != 0) {
            g_aggA_nm[tile * 32 + l] = tot_nm;
            g_aggA_x [tile * 32 + l] = tot_x;
            __threadfence();
            __syncwarp();
            if (l == 0) atomicExch(&g_stateA[tile], FLAG_AGG);

            int p_end = seg;
            for (;;) {
                int cnt = p_end < 32 ? p_end : 32;
                int s = FLAG_INC;
                if (l < cnt) {
                    int pp = bbase + p_end - 1 - l;
                    do { s = atomicAdd(&g_stateA[pp], 0); } while (s < FLAG_AGG);
                }
                unsigned incmask = __ballot_sync(0xffffffffu, (s == FLAG_INC) && (l < cnt));
                __threadfence();
                int li = incmask ? (__ffs(incmask) - 1) : -1;
                int nagg = (li >= 0) ? li : cnt;
                for (int j = 0; j < nagg; j++) {
                    int pidx = (bbase + p_end - 1 - j) * 32 + l;
                    f4add(ex_nm, __ldcg(&g_aggA_nm[pidx]));
                    f4add(ex_x,  __ldcg(&g_aggA_x [pidx]));
                }
                if (li >= 0) {
                    int pidx = (bbase + p_end - 1 - li) * 32 + l;
                    f4add(ex_nm, __ldcg(&g_incA_nm[pidx]));
                    f4add(ex_x,  __ldcg(&g_incA_x [pidx]));
                    break;
                }
                p_end -= cnt;
            }
        }
        float4 in_nm = ex_nm, in_x = ex_x;
        f4add(in_nm, tot_nm); f4add(in_x, tot_x);
        g_incA_nm[tile * 32 + l] = in_nm;
        g_incA_x [tile * 32 + l] = in_x;
        __threadfence();
        __syncwarp();
        if (l == 0) atomicExch(&g_stateA[tile], FLAG_INC);
        s_a[l] = ex_nm; s_b[l] = ex_x;
    }
    __syncthreads();
    float4 base_n = s_a[l], base_x = s_b[l];
    f4add(base_n, we_nm); f4add(base_x, we_x);

    // ================= Phase 2: local sum of ((x-mean)*nm)^2 =================
    float4 cn = base_n, cx = base_x;
    float4 lss = make_float4(0.f, 0.f, 0.f, 0.f);
    #pragma unroll 8
    for (int t = 0; t < SPW; t++) {
        float4 xv = x4[rowbase + t * 32];
        #define STEP2(k, bits)                                            \
        {                                                                 \
            float nm = (bits & (1u << t)) ? 1.f : 0.f;                    \
            cn.k += nm; cx.k += xv.k;                                     \
            float n = fmaxf(cn.k, 1.f);                                   \
            float mean = cx.k * rcpa(n);                                  \
            float d = (xv.k - mean) * nm;                                 \
            lss.k += d * d;                                               \
        }
        STEP2(x, nb0) STEP2(y, nb1) STEP2(z, nb2) STEP2(w, nb3)
        #undef STEP2
    }
    __syncthreads();
    s_a[tid] = lss;
    __syncthreads();
    float4 we_s = make_float4(0.f, 0.f, 0.f, 0.f);
    for (int ww = 0; ww < w; ww++) f4add(we_s, s_a[ww * 32 + l]);
    float4 tot_s;
    if (w == 0) {
        tot_s = s_a[l];
        f4add(tot_s, s_a[32 + l]); f4add(tot_s, s_a[64 + l]); f4add(tot_s, s_a[96 + l]);
    }
    __syncthreads();

    // ================= Lookback C (warp 0) =================
    if (w == 0) {
        float4 ex_s = make_float4(0.f, 0.f, 0.f, 0.f);
        if (seg != 0) {
            g_aggC[tile * 32 + l] = tot_s;
            __threadfence();
            __syncwarp();
            if (l == 0) atomicExch(&g_stateC[tile], FLAG_AGG);

            int p_end = seg;
            for (;;) {
                int cnt = p_end < 32 ? p_end : 32;
                int s = FLAG_INC;
                if (l < cnt) {
                    int pp = bbase + p_end - 1 - l;
                    do { s = atomicAdd(&g_stateC[pp], 0); } while (s < FLAG_AGG);
                }
                unsigned incmask = __ballot_sync(0xffffffffu, (s == FLAG_INC) && (l < cnt));
                __threadfence();
                int li = incmask ? (__ffs(incmask) - 1) : -1;
                int nagg = (li >= 0) ? li : cnt;
                for (int j = 0; j < nagg; j++)
                    f4add(ex_s, __ldcg(&g_aggC[(bbase + p_end - 1 - j) * 32 + l]));
                if (li >= 0) {
                    f4add(ex_s, __ldcg(&g_incC[(bbase + p_end - 1 - li) * 32 + l]));
                    break;
                }
                p_end -= cnt;
            }
        }
        float4 in_s = ex_s; f4add(in_s, tot_s);
        g_incC[tile * 32 + l] = in_s;
        __threadfence();
        __syncwarp();
        if (l == 0) atomicExch(&g_stateC[tile], FLAG_INC);
        s_a[l] = ex_s;
    }
    __syncthreads();
    float4 base_s = s_a[l];
    f4add(base_s, we_s);

    // ================= Phase 3: normalize + clip, write out =================
    cn = base_n; cx = base_x;
    float4 cs = base_s;
    const float VMIN = STD_MIN * STD_MIN;
    #pragma unroll 8
    for (int t = 0; t < SPW; t++) {
        float4 xv = __ldcs(&x4[rowbase + t * 32]);
        float4 ov;
        #define STEP3(k, bits)                                            \
        {                                                                 \
            float nm = (bits & (1u << t)) ? 1.f : 0.f;                    \
            cn.k += nm; cx.k += xv.k;                                     \
            float n = fmaxf(cn.k, 1.f);                                   \
            float rn = rcpa(n);                                           \
            float mean = cx.k * rn;                                       \
            float num = xv.k - mean;                                      \
            float d = num * nm;                                           \
            cs.k += d * d;                                                \
            float var = cs.k * rn;                                        \
            float res = (var > VMIN) ? num * rsqrtf(var) : num;           \
            ov.k = fminf(fmaxf(res, -MAX_VAL), MAX_VAL);                  \
        }
        STEP3(x, nb0) STEP3(y, nb1) STEP3(z, nb2) STEP3(w, nb3)
        #undef STEP3
        __stcs(&o4[rowbase + t * 32], ov);
    }
}

extern "C" void kernel_launch(void* const* d_in, const int* in_sizes, int n_in,
                              void* d_out, int out_size) {
    const float* x = (const float*)d_in[0];
    const float* m = (const float*)d_in[1];
    float* out = (float*)d_out;

    k_main<<<NTILE, 128>>>(x, m, out);
}

// round 16
// speedup vs baseline: 1.7037x; 1.0707x over previous
#include <cuda_runtime.h>

// CausalRevIN: B=16, T=8192, C=128, fp32.
// r8 structure exactly (1024 CTA-tiles = blockIdx, 4 warps x 32t, windowed
// lookback, atomic polls, single resident wave). No init kernel: per-launch
// epoch from a warp0/lane0 ticket whose latency hides under phase-1 loads.

#define BB 16
#define TT 8192
#define TILE_T 128
#define SPW 32
#define SPB 64                  // tiles per series
#define NTILE (BB * SPB)        // 1024

#define STD_MIN 1e-5f
#define MAX_VAL 100.0f

__device__ float4 g_aggA_nm[NTILE * 32];
__device__ float4 g_aggA_x [NTILE * 32];
__device__ float4 g_incA_nm[NTILE * 32];
__device__ float4 g_incA_x [NTILE * 32];
__device__ float4 g_aggC   [NTILE * 32];
__device__ float4 g_incC   [NTILE * 32];
__device__ int    g_stateA [NTILE];    // zero at module load; never reset
__device__ int    g_stateC [NTILE];
__device__ unsigned g_ticket;          // never reset; 1024 increments/launch

__device__ __forceinline__ void f4add(float4& a, const float4 b) {
    a.x += b.x; a.y += b.y; a.z += b.z; a.w += b.w;
}

__device__ __forceinline__ float rcpa(float x) {
    float r; asm("rcp.approx.f32 %0, %1;" : "=f"(r) : "f"(x)); return r;
}

__global__ void __launch_bounds__(128, 7) k_main(const float* __restrict__ x,
                                                 const float* __restrict__ m,
                                                 float* __restrict__ out) {
    __shared__ float4 s_a[128];
    __shared__ float4 s_b[128];

    const int tid  = threadIdx.x;
    const int tile = blockIdx.x;         // single resident wave -> safe
    const int b    = tile >> 6;
    const int seg  = tile & (SPB - 1);
    const int w    = tid >> 5;
    const int l    = tid & 31;
    const int bbase = b << 6;

    // Warp 0 lane 0 grabs the epoch ticket NOW; value used only after phase 1.
    unsigned traw = 0;
    if (w == 0 && l == 0) traw = atomicAdd(&g_ticket, 1u);

    const float4* __restrict__ x4 = (const float4*)x;
    const float4* __restrict__ m4 = (const float4*)m;
    float4* __restrict__ o4 = (float4*)out;
    const int rowbase = (b * TT + seg * TILE_T + w * SPW) * 32 + l;

    // ================= Phase 1: load, pack mask bits, sum x =================
    float4 sx = make_float4(0.f, 0.f, 0.f, 0.f);
    unsigned nb0 = 0, nb1 = 0, nb2 = 0, nb3 = 0;
    #pragma unroll 8
    for (int t = 0; t < SPW; t++) {
        float4 xv = x4[rowbase + t * 32];
        float4 mv = __ldcs(&m4[rowbase + t * 32]);
        f4add(sx, xv);
        if (mv.x == 0.f) nb0 |= 1u << t;
        if (mv.y == 0.f) nb1 |= 1u << t;
        if (mv.z == 0.f) nb2 |= 1u << t;
        if (mv.w == 0.f) nb3 |= 1u << t;
    }
    float4 snm = make_float4((float)__popc(nb0), (float)__popc(nb1),
                             (float)__popc(nb2), (float)__popc(nb3));
    s_a[tid] = snm; s_b[tid] = sx;
    __syncthreads();

    // exclusive prefix over warps (same lane) + CTA totals for warp 0
    float4 we_nm = make_float4(0.f, 0.f, 0.f, 0.f);
    float4 we_x  = make_float4(0.f, 0.f, 0.f, 0.f);
    for (int ww = 0; ww < w; ww++) { f4add(we_nm, s_a[ww * 32 + l]); f4add(we_x, s_b[ww * 32 + l]); }
    float4 tot_nm, tot_x;
    if (w == 0) {
        tot_nm = s_a[l];            tot_x = s_b[l];
        f4add(tot_nm, s_a[32 + l]); f4add(tot_x, s_b[32 + l]);
        f4add(tot_nm, s_a[64 + l]); f4add(tot_x, s_b[64 + l]);
        f4add(tot_nm, s_a[96 + l]); f4add(tot_x, s_b[96 + l]);
    }
    __syncthreads();

    // ================= Lookback A (warp 0) =================
    if (w == 0) {
        // epoch flags: launch e uses AGG=2e+1, INC=2e+2; stale values < AGG.
        traw = __shfl_sync(0xffffffffu, traw, 0);
        const int FLAG_AGG = (int)((traw >> 10) * 2u + 1u);
        const int FLAG_INC = FLAG_AGG + 1;

        float4 ex_nm = make_float4(0.f, 0.f, 0.f, 0.f);
        float4 ex_x  = make_float4(0.f, 0.f, 0.f, 0.f);
        if (seg != 0) {
            g_aggA_nm[tile * 32 + l] = tot_nm;
            g_aggA_x [tile * 32 + l] = tot_x;
            __threadfence();
            __syncwarp();
            if (l == 0) atomicExch(&g_stateA[tile], FLAG_AGG);

            int p_end = seg;
            for (;;) {
                int cnt = p_end < 32 ? p_end : 32;
                int s = FLAG_INC;
                if (l < cnt) {
                    int pp = bbase + p_end - 1 - l;
                    do { s = atomicAdd(&g_stateA[pp], 0); } while (s < FLAG_AGG);
                }
                unsigned incmask = __ballot_sync(0xffffffffu, (s == FLAG_INC) && (l < cnt));
                __threadfence();
                int li = incmask ? (__ffs(incmask) - 1) : -1;
                int nagg = (li >= 0) ? li : cnt;
                for (int j = 0; j < nagg; j++) {
                    int pidx = (bbase + p_end - 1 - j) * 32 + l;
                    f4add(ex_nm, __ldcg(&g_aggA_nm[pidx]));
                    f4add(ex_x,  __ldcg(&g_aggA_x [pidx]));
                }
                if (li >= 0) {
                    int pidx = (bbase + p_end - 1 - li) * 32 + l;
                    f4add(ex_nm, __ldcg(&g_incA_nm[pidx]));
                    f4add(ex_x,  __ldcg(&g_incA_x [pidx]));
                    break;
                }
                p_end -= cnt;
            }
        }
        float4 in_nm = ex_nm, in_x = ex_x;
        f4add(in_nm, tot_nm); f4add(in_x, tot_x);
        g_incA_nm[tile * 32 + l] = in_nm;
        g_incA_x [tile * 32 + l] = in_x;
        __threadfence();
        __syncwarp();
        if (l == 0) atomicExch(&g_stateA[tile], FLAG_INC);
        s_a[l] = ex_nm; s_b[l] = ex_x;
    }
    __syncthreads();
    float4 base_n = s_a[l], base_x = s_b[l];
    f4add(base_n, we_nm); f4add(base_x, we_x);

    // ================= Phase 2: local sum of ((x-mean)*nm)^2 =================
    float4 cn = base_n, cx = base_x;
    float4 lss = make_float4(0.f, 0.f, 0.f, 0.f);
    #pragma unroll 8
    for (int t = 0; t < SPW; t++) {
        float4 xv = x4[rowbase + t * 32];
        #define STEP2(k, bits)                                            \
        {                                                                 \
            float nm = (bits & (1u << t)) ? 1.f : 0.f;                    \
            cn.k += nm; cx.k += xv.k;                                     \
            float n = fmaxf(cn.k, 1.f);                                   \
            float mean = cx.k * rcpa(n);                                  \
            float d = (xv.k - mean) * nm;                                 \
            lss.k += d * d;                                               \
        }
        STEP2(x, nb0) STEP2(y, nb1) STEP2(z, nb2) STEP2(w, nb3)
        #undef STEP2
    }
    __syncthreads();
    s_a[tid] = lss;
    __syncthreads();
    float4 we_s = make_float4(0.f, 0.f, 0.f, 0.f);
    for (int ww = 0; ww < w; ww++) f4add(we_s, s_a[ww * 32 + l]);
    float4 tot_s;
    if (w == 0) {
        tot_s = s_a[l];
        f4add(tot_s, s_a[32 + l]); f4add(tot_s, s_a[64 + l]); f4add(tot_s, s_a[96 + l]);
    }
    __syncthreads();

    // ================= Lookback C (warp 0) =================
    if (w == 0) {
        const int FLAG_AGG = (int)((traw >> 10) * 2u + 1u);
        const int FLAG_INC = FLAG_AGG + 1;

        float4 ex_s = make_float4(0.f, 0.f, 0.f, 0.f);
        if (seg != 0) {
            g_aggC[tile * 32 + l] = tot_s;
            __threadfence();
            __syncwarp();
            if (l == 0) atomicExch(&g_stateC[tile], FLAG_AGG);

            int p_end = seg;
            for (;;) {
                int cnt = p_end < 32 ? p_end : 32;
                int s = FLAG_INC;
                if (l < cnt) {
                    int pp = bbase + p_end - 1 - l;
                    do { s = atomicAdd(&g_stateC[pp], 0); } while (s < FLAG_AGG);
                }
                unsigned incmask = __ballot_sync(0xffffffffu, (s == FLAG_INC) && (l < cnt));
                __threadfence();
                int li = incmask ? (__ffs(incmask) - 1) : -1;
                int nagg = (li >= 0) ? li : cnt;
                for (int j = 0; j < nagg; j++)
                    f4add(ex_s, __ldcg(&g_aggC[(bbase + p_end - 1 - j) * 32 + l]));
                if (li >= 0) {
                    f4add(ex_s, __ldcg(&g_incC[(bbase + p_end - 1 - li) * 32 + l]));
                    break;
                }
                p_end -= cnt;
            }
        }
        float4 in_s = ex_s; f4add(in_s, tot_s);
        g_incC[tile * 32 + l] = in_s;
        __threadfence();
        __syncwarp();
        if (l == 0) atomicExch(&g_stateC[tile], FLAG_INC);
        s_a[l] = ex_s;
    }
    __syncthreads();
    float4 base_s = s_a[l];
    f4add(base_s, we_s);

    // ================= Phase 3: normalize + clip, write out =================
    cn = base_n; cx = base_x;
    float4 cs = base_s;
    const float VMIN = STD_MIN * STD_MIN;
    #pragma unroll 8
    for (int t = 0; t < SPW; t++) {
        float4 xv = __ldcs(&x4[rowbase + t * 32]);
        float4 ov;
        #define STEP3(k, bits)                                            \
        {                                                                 \
            float nm = (bits & (1u << t)) ? 1.f : 0.f;                    \
            cn.k += nm; cx.k += xv.k;                                     \
            float n = fmaxf(cn.k, 1.f);                                   \
            float rn = rcpa(n);                                           \
            float mean = cx.k * rn;                                       \
            float num = xv.k - mean;                                      \
            float d = num * nm;                                           \
            cs.k += d * d;                                                \
            float var = cs.k * rn;                                        \
            float res = (var > VMIN) ? num * rsqrtf(var) : num;           \
            ov.k = fminf(fmaxf(res, -MAX_VAL), MAX_VAL);                  \
        }
        STEP3(x, nb0) STEP3(y, nb1) STEP3(z, nb2) STEP3(w, nb3)
        #undef STEP3
        __stcs(&o4[rowbase + t * 32], ov);
    }
}

extern "C" void kernel_launch(void* const* d_in, const int* in_sizes, int n_in,
                              void* d_out, int out_size) {
    const float* x = (const float*)d_in[0];
    const float* m = (const float*)d_in[1];
    float* out = (float*)d_out;

    k_main<<<NTILE, 128>>>(x, m, out);
}